// round 1
// baseline (speedup 1.0000x reference)
#include <cuda_runtime.h>
#include <math.h>

// ----------------------------------------------------------------------------
// QuantumBranch: expz0(t) for a fixed-theta 3-qubit circuit is EXACTLY a
// degree-12 trigonometric polynomial in (pi*t):
//   out(t) = a0 + sum_{k=1..12} a_k cos(k*pi*t) + b_k sin(k*pi*t)
// (feature-layer RY eigenphases are +/-{1,2,3}*pi*t/2; all phase sums are
//  integer multiples of pi*t up to 6 in amplitude, 12 in probability).
// Precompute the 25 coefficients from 25 direct circuit evaluations (real DFT
// with exact orthogonality on t_m = 2m/25), then evaluate the polynomial per
// element with a Chebyshev recurrence.
// ----------------------------------------------------------------------------

#define NSAMP 25
#define NHARM 12
#define PI_F 3.14159265358979323846f

__device__ float g_coef[NSAMP];   // [0..12] = a_k, [13..24] = b_{k-12}

struct cf { float re, im; };

// Generic 2x2 complex gate on `wire` of an 8-amplitude state.
// State index k = q0*4 + q1*2 + q2 (matches state[b, q0, q1, q2]).
__device__ __forceinline__ void gate1q(cf* s, int wire,
    float u00r, float u00i, float u01r, float u01i,
    float u10r, float u10i, float u11r, float u11i)
{
    const int str = 4 >> wire;
    #pragma unroll
    for (int k = 0; k < 8; k++) {
        if (k & str) continue;
        cf a = s[k], b = s[k + str];
        s[k].re       = u00r*a.re - u00i*a.im + u01r*b.re - u01i*b.im;
        s[k].im       = u00r*a.im + u00i*a.re + u01r*b.im + u01i*b.re;
        s[k + str].re = u10r*a.re - u10i*a.im + u11r*b.re - u11i*b.im;
        s[k + str].im = u10r*a.im + u10i*a.re + u11r*b.im + u11i*b.re;
    }
}

__device__ __forceinline__ void cnot(cf* s, int ctrl, int tgt)
{
    const int sc = 4 >> ctrl, st = 4 >> tgt;
    #pragma unroll
    for (int k = 0; k < 8; k++) {
        if (!(k & sc) || (k & st)) continue;
        cf tmp = s[k]; s[k] = s[k + st]; s[k + st] = tmp;
    }
}

// One ansatz layer: per qubit RZ(th[i,0]) RX(th[i,1]) RZ(th[i,2]), then the
// CNOT ring (0->1, 1->2, 2->0), matching the reference order.
__device__ void ansatz(cf* s, const float* th)
{
    #pragma unroll
    for (int i = 0; i < 3; i++) {
        float a = th[i*3 + 0];
        float c = cosf(0.5f*a), z = sinf(0.5f*a);
        gate1q(s, i, c, -z, 0.f, 0.f, 0.f, 0.f, c, z);          // RZ
        a = th[i*3 + 1];
        c = cosf(0.5f*a); z = sinf(0.5f*a);
        gate1q(s, i, c, 0.f, 0.f, -z, 0.f, -z, c, 0.f);         // RX
        a = th[i*3 + 2];
        c = cosf(0.5f*a); z = sinf(0.5f*a);
        gate1q(s, i, c, -z, 0.f, 0.f, 0.f, 0.f, c, z);          // RZ
    }
    cnot(s, 0, 1); cnot(s, 1, 2); cnot(s, 2, 0);
}

__device__ void feature(cf* s, float t)
{
    #pragma unroll
    for (int i = 0; i < 3; i++) {
        float phi = PI_F * t * (float)(i + 1);
        float c = cosf(0.5f*phi), z = sinf(0.5f*phi);
        gate1q(s, i, c, 0.f, -z, 0.f, z, 0.f, c, 0.f);          // RY
    }
}

// Direct circuit evaluation at one t.
__device__ float eval_circuit(const float* theta, float t)
{
    cf s[8];
    #pragma unroll
    for (int k = 0; k < 8; k++) { s[k].re = 0.f; s[k].im = 0.f; }
    s[0].re = 1.f;
    ansatz(s, theta);
    feature(s, t);
    ansatz(s, theta + 9);
    feature(s, t);
    ansatz(s, theta + 18);
    float e = 0.f;
    #pragma unroll
    for (int k = 0; k < 8; k++) {
        float p = s[k].re*s[k].re + s[k].im*s[k].im;
        e += (k < 4) ? p : -p;   // Z on qubit 0 (bit value 4)
    }
    return e;
}

// 25 circuit evaluations at t_m = 2m/25, then exact real-DFT inversion.
__global__ void precompute_kernel(const float* __restrict__ theta)
{
    __shared__ float f[NSAMP];
    const int j = threadIdx.x;
    if (j < NSAMP)
        f[j] = eval_circuit(theta, 2.0f * (float)j / 25.0f);
    __syncthreads();
    if (j < NSAMP) {
        double sum = 0.0;
        if (j == 0) {
            for (int m = 0; m < NSAMP; m++) sum += (double)f[m];
            g_coef[0] = (float)(sum / 25.0);
        } else if (j <= NHARM) {
            for (int m = 0; m < NSAMP; m++)
                sum += (double)f[m] * cos(2.0 * M_PI * (double)(j*m) / 25.0);
            g_coef[j] = (float)(2.0 * sum / 25.0);
        } else {
            int k = j - NHARM;
            for (int m = 0; m < NSAMP; m++)
                sum += (double)f[m] * sin(2.0 * M_PI * (double)(k*m) / 25.0);
            g_coef[j] = (float)(2.0 * sum / 25.0);
        }
    }
}

// Per-element polynomial evaluation. Chebyshev recurrence:
//   c_{k+1} = 2 c1 c_k - c_{k-1},  s_{k+1} = 2 c1 s_k - s_{k-1}
__device__ __forceinline__ float eval_poly(float t, const float* a, const float* b)
{
    float s1, c1;
    __sincosf(PI_F * t, &s1, &c1);
    float acc = fmaf(a[1], c1, a[0]);
    acc = fmaf(b[1], s1, acc);
    const float twoc = c1 + c1;
    float ckm = 1.f, ck = c1, skm = 0.f, sk = s1;
    #pragma unroll
    for (int k = 2; k <= NHARM; k++) {
        float cn = fmaf(twoc, ck, -ckm);
        float sn = fmaf(twoc, sk, -skm);
        acc = fmaf(a[k], cn, acc);
        acc = fmaf(b[k], sn, acc);
        ckm = ck; ck = cn;
        skm = sk; sk = sn;
    }
    return acc;
}

__global__ void __launch_bounds__(256)
eval_kernel(const float* __restrict__ t, float* __restrict__ out, int n)
{
    // Coefficients into registers once per thread (amortized over 4 elements).
    float a[NHARM + 1], b[NHARM + 1];
    #pragma unroll
    for (int k = 0; k <= NHARM; k++) a[k] = g_coef[k];
    b[0] = 0.f;
    #pragma unroll
    for (int k = 1; k <= NHARM; k++) b[k] = g_coef[NHARM + k];

    const int i4 = (blockIdx.x * blockDim.x + threadIdx.x) * 4;
    if (i4 + 3 < n) {
        float4 tv = *reinterpret_cast<const float4*>(t + i4);
        float4 ov;
        ov.x = eval_poly(tv.x, a, b);
        ov.y = eval_poly(tv.y, a, b);
        ov.z = eval_poly(tv.z, a, b);
        ov.w = eval_poly(tv.w, a, b);
        *reinterpret_cast<float4*>(out + i4) = ov;
    } else {
        for (int i = i4; i < n; i++)
            out[i] = eval_poly(t[i], a, b);
    }
}

extern "C" void kernel_launch(void* const* d_in, const int* in_sizes, int n_in,
                              void* d_out, int out_size)
{
    const float* t;
    const float* theta;
    // theta has exactly 27 elements; t has B elements. Detect order defensively.
    if (n_in >= 2 && in_sizes[0] == 27 && in_sizes[1] != 27) {
        theta = (const float*)d_in[0];
        t     = (const float*)d_in[1];
    } else {
        t     = (const float*)d_in[0];
        theta = (const float*)d_in[1];
    }
    float* out = (float*)d_out;
    const int n = out_size;

    precompute_kernel<<<1, 32>>>(theta);

    const int threads = 256;
    const int nthread = (n + 3) / 4;
    const int blocks = (nthread + threads - 1) / threads;
    eval_kernel<<<blocks, threads>>>(t, out, n);
}

// round 2
// speedup vs baseline: 4.1811x; 4.1811x over previous
#include <cuda_runtime.h>
#include <math.h>

// ----------------------------------------------------------------------------
// QuantumBranch: expz0(t) for fixed theta is EXACTLY a degree-12 trig
// polynomial in (pi*t). Pipeline:
//   1) precompute_kernel (1 block, 512 threads):
//      - 25 direct fp32 circuit evaluations at t_m = 2m/25
//      - exact real-DFT inversion (fp32 twiddles, args reduced mod 25)
//      - build a 512-interval Hermite-cubic table (power basis, float4/interval)
//   2) eval_kernel: per element, table lookup + 3 FMA (Horner on u in [0,1)).
// Spline error bound: h^4/384 * max|f''''| ~ 1.5e-7 at h=1/512  << 1e-3 tol.
// ----------------------------------------------------------------------------

#define NSAMP 25
#define NHARM 12
#define TBL   512
#define PI_F  3.14159265358979323846f

__device__ float4 g_table[TBL];

struct cf { float re, im; };

// Generic 2x2 complex gate on `wire` of an 8-amplitude state.
// State index k = q0*4 + q1*2 + q2 (matches state[b, q0, q1, q2]).
__device__ __forceinline__ void gate1q(cf* s, int wire,
    float u00r, float u00i, float u01r, float u01i,
    float u10r, float u10i, float u11r, float u11i)
{
    const int str = 4 >> wire;
    #pragma unroll
    for (int k = 0; k < 8; k++) {
        if (k & str) continue;
        cf a = s[k], b = s[k + str];
        s[k].re       = u00r*a.re - u00i*a.im + u01r*b.re - u01i*b.im;
        s[k].im       = u00r*a.im + u00i*a.re + u01r*b.im + u01i*b.re;
        s[k + str].re = u10r*a.re - u10i*a.im + u11r*b.re - u11i*b.im;
        s[k + str].im = u10r*a.im + u10i*a.re + u11r*b.im + u11i*b.re;
    }
}

__device__ __forceinline__ void cnot(cf* s, int ctrl, int tgt)
{
    const int sc = 4 >> ctrl, st = 4 >> tgt;
    #pragma unroll
    for (int k = 0; k < 8; k++) {
        if (!(k & sc) || (k & st)) continue;
        cf tmp = s[k]; s[k] = s[k + st]; s[k + st] = tmp;
    }
}

__device__ void ansatz(cf* s, const float* th)
{
    #pragma unroll
    for (int i = 0; i < 3; i++) {
        float a = th[i*3 + 0];
        float c, z; __sincosf(0.5f*a, &z, &c);
        gate1q(s, i, c, -z, 0.f, 0.f, 0.f, 0.f, c, z);          // RZ
        a = th[i*3 + 1];
        __sincosf(0.5f*a, &z, &c);
        gate1q(s, i, c, 0.f, 0.f, -z, 0.f, -z, c, 0.f);         // RX
        a = th[i*3 + 2];
        __sincosf(0.5f*a, &z, &c);
        gate1q(s, i, c, -z, 0.f, 0.f, 0.f, 0.f, c, z);          // RZ
    }
    cnot(s, 0, 1); cnot(s, 1, 2); cnot(s, 2, 0);
}

__device__ void feature(cf* s, float t)
{
    #pragma unroll
    for (int i = 0; i < 3; i++) {
        float phi = PI_F * t * (float)(i + 1);
        float c, z; __sincosf(0.5f*phi, &z, &c);
        gate1q(s, i, c, 0.f, -z, 0.f, z, 0.f, c, 0.f);          // RY
    }
}

__device__ float eval_circuit(const float* theta, float t)
{
    cf s[8];
    #pragma unroll
    for (int k = 0; k < 8; k++) { s[k].re = 0.f; s[k].im = 0.f; }
    s[0].re = 1.f;
    ansatz(s, theta);
    feature(s, t);
    ansatz(s, theta + 9);
    feature(s, t);
    ansatz(s, theta + 18);
    float e = 0.f;
    #pragma unroll
    for (int k = 0; k < 8; k++) {
        float p = s[k].re*s[k].re + s[k].im*s[k].im;
        e += (k < 4) ? p : -p;   // Z on qubit 0 (bit value 4)
    }
    return e;
}

// One block, TBL threads: circuit samples -> DFT coefficients -> cubic table.
__global__ void precompute_kernel(const float* __restrict__ theta)
{
    __shared__ float fs[NSAMP];
    __shared__ float ca[NHARM + 1], cb[NHARM + 1];
    const int tid = threadIdx.x;

    if (tid < NSAMP)
        fs[tid] = eval_circuit(theta, 2.0f * (float)tid / 25.0f);
    __syncthreads();

    if (tid < NSAMP) {
        float sum = 0.f;
        if (tid == 0) {
            for (int m = 0; m < NSAMP; m++) sum += fs[m];
            ca[0] = sum * (1.0f / 25.0f);
            cb[0] = 0.f;
        } else if (tid <= NHARM) {
            for (int m = 0; m < NSAMP; m++) {
                int r = (tid * m) % 25;
                float c, s; sincospif(2.0f * (float)r / 25.0f, &s, &c);
                sum += fs[m] * c;
            }
            ca[tid] = sum * (2.0f / 25.0f);
        } else {
            int k = tid - NHARM;
            for (int m = 0; m < NSAMP; m++) {
                int r = (k * m) % 25;
                float c, s; sincospif(2.0f * (float)r / 25.0f, &s, &c);
                sum += fs[m] * s;
            }
            cb[k] = sum * (2.0f / 25.0f);
        }
    }
    __syncthreads();

    // Hermite cubic per interval [tid/TBL, (tid+1)/TBL), power basis in u.
    if (tid < TBL) {
        float fv2[2], Dv2[2];
        #pragma unroll
        for (int e = 0; e < 2; e++) {
            float tt = (float)(tid + e) * (1.0f / (float)TBL);
            float c1, s1; sincospif(tt, &s1, &c1);   // cos(pi t), sin(pi t)
            float fv = fmaf(ca[1], c1, ca[0]);
            fv = fmaf(cb[1], s1, fv);
            float gv = cb[1]*c1 - ca[1]*s1;          // k=1 term of f'/pi
            const float twoc = c1 + c1;
            float ckm = 1.f, ck = c1, skm = 0.f, sk = s1;
            #pragma unroll
            for (int k = 2; k <= NHARM; k++) {
                float cn = fmaf(twoc, ck, -ckm);
                float sn = fmaf(twoc, sk, -skm);
                fv = fmaf(ca[k], cn, fv);
                fv = fmaf(cb[k], sn, fv);
                gv = fmaf((float)k, cb[k]*cn - ca[k]*sn, gv);
                ckm = ck; ck = cn; skm = sk; sk = sn;
            }
            fv2[e] = fv;
            Dv2[e] = gv * (PI_F / (float)TBL);       // f'(t) * h
        }
        float f0 = fv2[0], f1 = fv2[1], D0 = Dv2[0], D1 = Dv2[1];
        float p0 = f0;
        float p1 = D0;
        float p2 = 3.f*(f1 - f0) - 2.f*D0 - D1;
        float p3 = 2.f*(f0 - f1) + D0 + D1;
        g_table[tid] = make_float4(p0, p1, p2, p3);
    }
}

__device__ __forceinline__ float eval_elem(float tt, const float4* tbl)
{
    float x = tt * (float)TBL;
    int i = (int)x;
    i = max(0, min(i, TBL - 1));
    float u = x - (float)i;
    float4 c = tbl[i];
    return fmaf(fmaf(fmaf(c.w, u, c.z), u, c.y), u, c.x);
}

__global__ void __launch_bounds__(256)
eval_kernel(const float* __restrict__ t, float* __restrict__ out, int n)
{
    __shared__ float4 tbl[TBL];
    for (int i = threadIdx.x; i < TBL; i += blockDim.x)
        tbl[i] = g_table[i];
    __syncthreads();

    const int nvec = n >> 2;
    const int stride = gridDim.x * blockDim.x;
    for (int v = blockIdx.x * blockDim.x + threadIdx.x; v < nvec; v += stride) {
        float4 tv = reinterpret_cast<const float4*>(t)[v];
        float4 ov;
        ov.x = eval_elem(tv.x, tbl);
        ov.y = eval_elem(tv.y, tbl);
        ov.z = eval_elem(tv.z, tbl);
        ov.w = eval_elem(tv.w, tbl);
        reinterpret_cast<float4*>(out)[v] = ov;
    }
    // tail (n not multiple of 4)
    for (int i = (nvec << 2) + blockIdx.x * blockDim.x + threadIdx.x; i < n;
         i += stride)
        out[i] = eval_elem(t[i], tbl);
}

extern "C" void kernel_launch(void* const* d_in, const int* in_sizes, int n_in,
                              void* d_out, int out_size)
{
    const float* t;
    const float* theta;
    if (n_in >= 2 && in_sizes[0] == 27 && in_sizes[1] != 27) {
        theta = (const float*)d_in[0];
        t     = (const float*)d_in[1];
    } else {
        t     = (const float*)d_in[0];
        theta = (const float*)d_in[1];
    }
    float* out = (float*)d_out;
    const int n = out_size;

    precompute_kernel<<<1, TBL>>>(theta);

    // 512 blocks: enough waves for full-chip DRAM BW, but bounded table-reload
    // traffic (512 * 8KB = 4MB of L2 broadcast).
    eval_kernel<<<512, 256>>>(t, out, n);
}